// round 2
// baseline (speedup 1.0000x reference)
#include <cuda_runtime.h>

// CRF loss, T=512, B=1024, K=48.
// Linear-space forward recursion: smem holds P[j] = exp(alpha_j - C), C tracked
// redundantly per-thread (identical arithmetic from identical smem reads).
// Per step: one smem exchange + ONE barrier; no reductions on the critical path.

#define TT 512
#define BB 1024
#define KK 48
#define START_TAG 46
#define STOP_TAG  47

__device__ float g_partial[BB];
__device__ int   g_count = 0;   // last block resets to 0 (graph-replay safe)

__global__ void __launch_bounds__(64, 8) crf_kernel(
    const float* __restrict__ feats,
    const float* __restrict__ trans,
    const int*   __restrict__ tags,
    const int*   __restrict__ lengths,
    float*       __restrict__ out)
{
    __shared__ __align__(16) float s_p[2][64];
    __shared__ float s_red[2];
    __shared__ float s_trans[KK * KK];
    __shared__ int   s_islast;

    const int b    = blockIdx.x;
    const int tid  = threadIdx.x;
    const int lane = tid & 31;
    const int warp = tid >> 5;
    const bool active = (tid < KK);
    const int len = __ldg(lengths + b);

    // raw transitions in smem (gold lookups + STOP row)
    for (int i = tid; i < KK * KK; i += 64) s_trans[i] = trans[i];

    // per-thread row of exp(transitions): et[i] = exp(trans[tid, i])
    float et[KK];
    if (active) {
        #pragma unroll
        for (int i = 0; i < KK; i++)
            et[i] = __expf(trans[tid * KK + i]);   // exp(-10000) == 0.0f
    }

    // P_0 = basis vector at START; slots 48..63 stay 0 forever
    s_p[0][tid] = (tid == START_TAG) ? 1.0f : 0.0f;
    s_p[1][tid] = 0.0f;

    const float* fb = feats + b * KK;              // feats[t*B*K + b*K + j]
    const size_t FS = (size_t)BB * KK;

    // feat register pipeline, depth 4 (covers DRAM latency on critical block)
    float f1 = 0.f, f2 = 0.f, f3 = 0.f, f4 = 0.f;
    if (active) {
        f1 = __ldg(fb + tid);
        if (1 < len) f2 = __ldg(fb + 1 * FS + tid);
        if (2 < len) f3 = __ldg(fb + 2 * FS + tid);
        if (3 < len) f4 = __ldg(fb + 3 * FS + tid);
    }
    float C = 0.0f;
    __syncthreads();

    int buf = 0;
    for (int t = 0; t < len; t++) {
        float fcur = f1;
        f1 = f2; f2 = f3; f3 = f4;
        f4 = (active && (t + 4 < len)) ? __ldg(fb + (size_t)(t + 4) * FS + tid) : 0.0f;

        if (active) {
            const float4* ev = (const float4*)(s_p[buf]);
            float4 e0 = ev[0];                     // broadcast, conflict-free
            float p0 = e0.x;
            // renormalizer + C update (identical on all threads; off critical path)
            float k  = (p0 > 0.0f) ? __frcp_rn(p0) : 1.0f;
            C       += (p0 > 0.0f) ? __logf(p0)   : 0.0f;
            float mul = __expf(fcur) * k;

            float s0 = e0.x * et[0];
            float s1 = e0.y * et[1];
            float s2 = e0.z * et[2];
            float s3 = e0.w * et[3];
            #pragma unroll
            for (int q = 1; q < KK / 4; q++) {
                float4 e = ev[q];
                s0 = fmaf(e.x, et[4*q + 0], s0);
                s1 = fmaf(e.y, et[4*q + 1], s1);
                s2 = fmaf(e.z, et[4*q + 2], s2);
                s3 = fmaf(e.w, et[4*q + 3], s3);
            }
            s_p[buf ^ 1][tid] = ((s0 + s1) + (s2 + s3)) * mul;
        }
        __syncthreads();                            // one barrier per step
        buf ^= 1;
    }

    // log_z = C + log( sum_j P[j] * exp(trans[STOP, j]) )   (pure linear)
    float v = active ? s_p[buf][tid] * __expf(s_trans[STOP_TAG * KK + tid]) : 0.0f;
    #pragma unroll
    for (int o = 16; o; o >>= 1) v += __shfl_xor_sync(~0u, v, o);
    if (lane == 0) s_red[warp] = v;
    __syncthreads();
    float logz = C + __logf(s_red[0] + s_red[1]);
    __syncthreads();

    // gold score: parallel over t, block reduce
    const int* tg = tags + b * TT;
    float g = 0.0f;
    for (int t = tid; t < len; t += 64) {
        int nxt = __ldg(tg + t);
        int prv = (t == 0) ? START_TAG : __ldg(tg + t - 1);
        g += s_trans[nxt * KK + prv] + __ldg(fb + (size_t)t * FS + nxt);
    }
    #pragma unroll
    for (int o = 16; o; o >>= 1) g += __shfl_xor_sync(~0u, g, o);
    if (lane == 0) s_red[warp] = g;
    __syncthreads();

    if (tid == 0) {
        float gold = s_red[0] + s_red[1]
                   + s_trans[STOP_TAG * KK + __ldg(tg + len - 1)];
        g_partial[b] = logz - gold;
        __threadfence();
        int prev = atomicAdd(&g_count, 1);
        s_islast = (prev == BB - 1) ? 1 : 0;
    }
    __syncthreads();

    // last block: deterministic fixed-order final reduction, reset counter
    if (s_islast) {
        float a = 0.0f;
        #pragma unroll
        for (int i = 0; i < BB / 64; i++)           // 16 strided values, fixed order
            a += g_partial[tid + i * 64];
        #pragma unroll
        for (int o = 16; o; o >>= 1) a += __shfl_xor_sync(~0u, a, o);
        if (lane == 0) s_red[warp] = a;
        __syncthreads();
        if (tid == 0) {
            out[0] = s_red[0] + s_red[1];
            g_count = 0;                            // replay-safe reset
        }
    }
}

extern "C" void kernel_launch(void* const* d_in, const int* in_sizes, int n_in,
                              void* d_out, int out_size) {
    const float* feats   = (const float*)d_in[0];
    const float* trans   = (const float*)d_in[1];
    const int*   tags    = (const int*)d_in[2];
    const int*   lengths = (const int*)d_in[3];
    crf_kernel<<<BB, 64>>>(feats, trans, tags, lengths, (float*)d_out);
}

// round 4
// speedup vs baseline: 1.6822x; 1.6822x over previous
#include <cuda_runtime.h>

// CRF loss, T=512, B=1024, K=48.
// One 32-thread warp per batch element. Lanes 0..23 own state pair (2l, 2l+1).
// Linear-space recursion with exact power-of-2 renormalization (int exponent
// accumulator, zero MUFU on the renorm path). P kept in smem DUPLICATED
// ({P_i,P_i}) so one LDS.128 feeds two fma.rn.f32x2 ops. No __syncthreads.
// R4 fix: the duplicated layout packs TWO states per 16B, so the matvec loop
// must run 24 iterations (R3 ran 12 -> dropped states 24..47 -> log(0)).

#define TT 512
#define BB 1024
#define KK 48
#define START_TAG 46
#define STOP_TAG  47
#define LN2F 0.6931471805599453f

__device__ float g_partial[BB];
__device__ int   g_count = 0;   // last block resets to 0 (graph-replay safe)

__device__ __forceinline__ unsigned long long pack2(float lo, float hi) {
    unsigned long long r;
    asm("mov.b64 %0, {%1, %2};" : "=l"(r) : "f"(lo), "f"(hi));
    return r;
}
__device__ __forceinline__ void unpack2(unsigned long long v, float& lo, float& hi) {
    asm("mov.b64 {%0, %1}, %2;" : "=f"(lo), "=f"(hi) : "l"(v));
}
__device__ __forceinline__ unsigned long long fma2(unsigned long long a,
                                                   unsigned long long b,
                                                   unsigned long long c) {
    unsigned long long d;
    asm("fma.rn.f32x2 %0, %1, %2, %3;" : "=l"(d) : "l"(a), "l"(b), "l"(c));
    return d;
}
__device__ __forceinline__ unsigned long long add2(unsigned long long a,
                                                   unsigned long long b) {
    unsigned long long d;
    asm("add.rn.f32x2 %0, %1, %2;" : "=l"(d) : "l"(a), "l"(b));
    return d;
}

__global__ void __launch_bounds__(32, 1) crf_kernel(
    const float* __restrict__ feats,
    const float* __restrict__ trans,
    const int*   __restrict__ tags,
    const int*   __restrict__ lengths,
    float*       __restrict__ out)
{
    __shared__ __align__(16) float2 s_pd[2][48];   // duplicated P, ping-pong
    __shared__ float s_trans[KK * KK];

    const int b    = blockIdx.x;
    const int lane = threadIdx.x;
    const bool act = (lane < 24);
    const int s0 = 2 * lane;        // owned states (act lanes)
    const int s1 = 2 * lane + 1;
    const int len = __ldg(lengths + b);

    for (int i = lane; i < KK * KK; i += 32) s_trans[i] = trans[i];
    // init duplicated P = basis at START
    for (int i = lane; i < 48; i += 32) {
        float v = (i == START_TAG) ? 1.0f : 0.0f;
        s_pd[0][i] = make_float2(v, v);
        s_pd[1][i] = make_float2(0.0f, 0.0f);
    }
    __syncwarp();

    // loop-invariant packed transition rows: et2[i] = {e^T[s0,i], e^T[s1,i]}
    unsigned long long et2[KK];
    if (act) {
        #pragma unroll
        for (int i = 0; i < KK; i++)
            et2[i] = pack2(__expf(s_trans[s0 * KK + i]),
                           __expf(s_trans[s1 * KK + i]));  // exp(-1e4) == 0
    }

    const float* fb = feats + b * KK;
    const size_t FS = (size_t)BB * KK;

    // feat prefetch pipeline (float2 per lane: states s0,s1), depth 4
    float2 f1 = {0,0}, f2 = {0,0}, f3 = {0,0}, f4 = {0,0};
    if (act) {
        f1 = __ldg((const float2*)(fb + s0));
        if (1 < len) f2 = __ldg((const float2*)(fb + 1 * FS + s0));
        if (2 < len) f3 = __ldg((const float2*)(fb + 2 * FS + s0));
        if (3 < len) f4 = __ldg((const float2*)(fb + 3 * FS + s0));
    }
    int Cint = 0;
    __syncwarp();

    int buf = 0;
    #pragma unroll 1
    for (int t = 0; t < len; t++) {
        float2 fcur = f1;
        f1 = f2; f2 = f3; f3 = f4;
        if (act)
            f4 = (t + 4 < len) ? __ldg((const float2*)(fb + (size_t)(t + 4) * FS + s0))
                               : make_float2(0.0f, 0.0f);

        if (act) {
            const ulonglong2* pv = (const ulonglong2*)(s_pd[buf]);
            float p0s = s_pd[buf][0].x;                  // broadcast scalar LDS

            unsigned long long a0 = 0ull, a1 = 0ull, a2 = 0ull, a3 = 0ull;
            #pragma unroll
            for (int q = 0; q < 24; q++) {               // states 2q, 2q+1
                ulonglong2 e = pv[q];                    // broadcast LDS.128
                if (q & 1) {
                    a2 = fma2(e.x, et2[2*q],     a2);
                    a3 = fma2(e.y, et2[2*q + 1], a3);
                } else {
                    a0 = fma2(e.x, et2[2*q],     a0);
                    a1 = fma2(e.y, et2[2*q + 1], a1);
                }
            }
            unsigned long long s2 = add2(add2(a0, a2), add2(a1, a3));

            // exact power-of-2 renorm from P_0's exponent (off critical path)
            unsigned int pexp = __float_as_uint(p0s) >> 23;
            int pe = (pexp - 1u < 254u) ? (int)pexp - 127 : 0;  // 0 for 0/denorm
            Cint += pe;
            float k = __uint_as_float((unsigned)(127 - pe) << 23);

            float sl, sh;
            unpack2(s2, sl, sh);
            float p0n = sl * (__expf(fcur.x) * k);
            float p1n = sh * (__expf(fcur.y) * k);
            *(float4*)(&s_pd[buf ^ 1][s0]) = make_float4(p0n, p0n, p1n, p1n);
        }
        __syncwarp();
        buf ^= 1;
    }

    // log_z = Cint*ln2 + log( sum_j P_j * exp(trans[STOP, j]) )
    float v = 0.0f;
    if (act) {
        float P0 = s_pd[buf][s0].x;
        float P1 = s_pd[buf][s1].x;
        v = P0 * __expf(s_trans[STOP_TAG * KK + s0])
          + P1 * __expf(s_trans[STOP_TAG * KK + s1]);
    }
    #pragma unroll
    for (int o = 16; o; o >>= 1) v += __shfl_xor_sync(~0u, v, o);
    float logz = (float)Cint * LN2F + __logf(v);   // lane 0's Cint is valid

    // gold score: strided over t, warp reduce
    const int* tg = tags + b * TT;
    float g = 0.0f;
    for (int t = lane; t < len; t += 32) {
        int nxt = __ldg(tg + t);
        int prv = (t == 0) ? START_TAG : __ldg(tg + t - 1);
        g += s_trans[nxt * KK + prv] + __ldg(fb + (size_t)t * FS + nxt);
    }
    #pragma unroll
    for (int o = 16; o; o >>= 1) g += __shfl_xor_sync(~0u, g, o);

    int last = 0;
    if (lane == 0) {
        float gold = g + s_trans[STOP_TAG * KK + __ldg(tg + len - 1)];
        g_partial[b] = logz - gold;
        __threadfence();
        int prev = atomicAdd(&g_count, 1);
        last = (prev == BB - 1);
    }
    last = __shfl_sync(~0u, last, 0);

    // last block: deterministic fixed-order final reduction, reset counter
    if (last) {
        __threadfence();
        float a = 0.0f;
        #pragma unroll
        for (int i = 0; i < BB / 32; i++)
            a += g_partial[lane + i * 32];
        #pragma unroll
        for (int o = 16; o; o >>= 1) a += __shfl_xor_sync(~0u, a, o);
        if (lane == 0) {
            out[0] = a;
            g_count = 0;                           // replay-safe reset
        }
    }
}

extern "C" void kernel_launch(void* const* d_in, const int* in_sizes, int n_in,
                              void* d_out, int out_size) {
    const float* feats   = (const float*)d_in[0];
    const float* trans   = (const float*)d_in[1];
    const int*   tags    = (const int*)d_in[2];
    const int*   lengths = (const int*)d_in[3];
    crf_kernel<<<BB, 32>>>(feats, trans, tags, lengths, (float*)d_out);
}